// round 10
// baseline (speedup 1.0000x reference)
#include <cuda_runtime.h>
#include <cstdint>

#define DDIM   4096
#define M_ROWS 8192
#define N_ROWS 4096
#define KINT   (DDIM / 4)          // 1024 ints per row

__device__ __align__(256) int8_t g_qx[(size_t)M_ROWS * DDIM];
__device__ __align__(256) int8_t g_qw[(size_t)N_ROWS * DDIM];
__device__ float g_sa[M_ROWS];
__device__ float g_sw[N_ROWS];

__device__ __forceinline__ uint32_t smem_u32(const void* p) {
    uint32_t a;
    asm("{ .reg .u64 t; cvta.to.shared.u64 t, %1; cvt.u32.u64 %0, t; }" : "=r"(a) : "l"(p));
    return a;
}
__device__ __forceinline__ void cp16(uint32_t dst, const void* src) {
    asm volatile("cp.async.cg.shared.global [%0], [%1], 16;" :: "r"(dst), "l"(src) : "memory");
}
#define CP_COMMIT()  asm volatile("cp.async.commit_group;" ::: "memory")
#define CP_WAIT(n)   asm volatile("cp.async.wait_group %0;" :: "n"(n) : "memory")

__device__ __forceinline__ void ldsm4(uint32_t& r0, uint32_t& r1, uint32_t& r2, uint32_t& r3,
                                      uint32_t addr) {
    asm volatile("ldmatrix.sync.aligned.m8n8.x4.shared.b16 {%0,%1,%2,%3}, [%4];"
                 : "=r"(r0), "=r"(r1), "=r"(r2), "=r"(r3) : "r"(addr));
}
__device__ __forceinline__ void imma16832(int* c, const uint32_t* a, const uint32_t* b) {
    asm volatile(
        "mma.sync.aligned.m16n8k32.row.col.s32.s8.s8.s32 "
        "{%0,%1,%2,%3}, {%4,%5,%6,%7}, {%8,%9}, {%0,%1,%2,%3};\n"
        : "+r"(c[0]), "+r"(c[1]), "+r"(c[2]), "+r"(c[3])
        : "r"(a[0]), "r"(a[1]), "r"(a[2]), "r"(a[3]), "r"(b[0]), "r"(b[1]));
}

// ---------------- fused row-wise absmax int8 quantization ----------------
__global__ __launch_bounds__(256) void quant_fused_kernel(
    const float* __restrict__ x, const float* __restrict__ w,
    const float* __restrict__ scales)
{
    const int b    = blockIdx.x;
    const bool isx = (b < M_ROWS);
    const int row  = isx ? b : (b - M_ROWS);
    const int tid  = threadIdx.x;
    const float4* src4 = reinterpret_cast<const float4*>((isx ? x : w) + (size_t)row * DDIM);
    const float4* scl4 = reinterpret_cast<const float4*>(scales);

    float v[16];
    float m = 0.f;
    #pragma unroll
    for (int i = 0; i < 4; i++) {
        int g = i * 256 + tid;
        float4 xv = src4[g];
        float4 s  = scl4[g];
        float t0, t1, t2, t3;
        if (isx) { t0 = xv.x * s.x; t1 = xv.y * s.y; t2 = xv.z * s.z; t3 = xv.w * s.w; }
        else     { t0 = xv.x / s.x; t1 = xv.y / s.y; t2 = xv.z / s.z; t3 = xv.w / s.w; }
        v[i*4+0] = t0; v[i*4+1] = t1; v[i*4+2] = t2; v[i*4+3] = t3;
        m = fmaxf(m, fmaxf(fmaxf(fabsf(t0), fabsf(t1)), fmaxf(fabsf(t2), fabsf(t3))));
    }

    __shared__ float red[8];
    #pragma unroll
    for (int o = 16; o > 0; o >>= 1)
        m = fmaxf(m, __shfl_xor_sync(0xffffffffu, m, o));
    if ((tid & 31) == 0) red[tid >> 5] = m;
    __syncthreads();
    if (tid < 32) {
        float t = (tid < 8) ? red[tid] : 0.f;
        #pragma unroll
        for (int o = 4; o > 0; o >>= 1)
            t = fmaxf(t, __shfl_xor_sync(0xffffffffu, t, o));
        if (tid == 0) red[0] = fmaxf(t, 1e-8f);
    }
    __syncthreads();
    const float absmax = red[0];
    const float qs = 127.f / absmax;

    int* qrow = reinterpret_cast<int*>((isx ? g_qx : g_qw) + (size_t)row * DDIM);
    #pragma unroll
    for (int i = 0; i < 4; i++) {
        int g = i * 256 + tid;
        int packed = 0;
        #pragma unroll
        for (int j = 0; j < 4; j++) {
            float t = rintf(v[i*4+j] * qs);
            t = fminf(fmaxf(t, -127.f), 127.f);
            packed |= ((int)t & 0xff) << (8 * j);
        }
        qrow[g] = packed;
    }
    if (tid == 0) {
        if (isx) g_sa[row] = absmax * (1.f / 127.f);
        else     g_sw[row] = absmax * (1.f / 127.f);
    }
}

// ---------------- hybrid GEMM, issue-light load path ----------------
// CTA 128x128. Shared K-major tiles: 128-byte rows (32 ints of K per stage),
// 16B-unit XOR swizzle u^=(r&7). Loaded with 16B cp.async (4x fewer LSU ops).
//   dp4a warps 0-3: n[0:64). Strided ownership m=ty+16i, n=tx+8j so row&7
//     varies across lanes -> vectorized LDS.128 along K, conflict-free.
//   IMMA warps 4-7: n[64:128) via ldmatrix.x4 (R5-proven addressing).
// 3-stage ring, one __syncthreads per chunk.
#define BKI     32                    // K ints per chunk (= 128 bytes)
#define NCHUNK  (KINT / BKI)          // 32
#define A_BYTES (128 * 128)           // 16384 per stage
#define STAGEB  (2 * A_BYTES)         // 32768 (A then B)
#define SMEM_BYTES (3 * STAGEB)       // 98304

__global__ __launch_bounds__(256, 2) void gemm_hybrid_kernel(
    const float* __restrict__ bias, const float* __restrict__ scales,
    float* __restrict__ out)
{
    extern __shared__ int smem[];
    const uint32_t sb = smem_u32(smem);
    const int tid  = threadIdx.x;
    const int wid  = tid >> 5;
    const int lane = tid & 31;
    const int m0   = blockIdx.y * 128;
    const int n0   = blockIdx.x * 128;

    const int* qxi = reinterpret_cast<const int*>(g_qx);
    const int* qwi = reinterpret_cast<const int*>(g_qw);

    // loader: 4 A-cp16 + 4 B-cp16 per thread per stage (1024 units each tile)
    auto load_stage = [&](int c) {
        const uint32_t sbase = sb + (uint32_t)(c % 3) * STAGEB;
        #pragma unroll
        for (int j = 0; j < 4; j++) {
            int idx = j * 256 + tid;          // 0..1023
            int r = idx >> 3, u = idx & 7;
            uint32_t d = (uint32_t)(r * 128 + ((u ^ (r & 7)) << 4));
            cp16(sbase + d,           qxi + (size_t)(m0 + r) * KINT + c * BKI + u * 4);
            cp16(sbase + A_BYTES + d, qwi + (size_t)(n0 + r) * KINT + c * BKI + u * 4);
        }
    };

    if (wid < 4) {
        // ================= dp4a half: n in [0,64) =================
        const int ty = tid >> 3;     // 0..15, owns m rows ty+16i
        const int tx = tid & 7;      // 0..7,  owns n cols tx+8j
        int acc[8][8];
        #pragma unroll
        for (int i = 0; i < 8; i++)
            #pragma unroll
            for (int j = 0; j < 8; j++) acc[i][j] = 0;

        // per-row int4 indices (16B units), row&7 varies across lanes
        int aIdx[8], bIdx[8];
        #pragma unroll
        for (int i = 0; i < 8; i++) {
            int r = ty + 16 * i;
            aIdx[i] = r * 8;              // + (u ^ (r&7))
        }
        const int aSw = ty & 7;
        #pragma unroll
        for (int j = 0; j < 8; j++) {
            int r = tx + 8 * j;
            bIdx[j] = r * 8;
        }
        const int bSw = tx & 7;

        load_stage(0); CP_COMMIT();
        load_stage(1); CP_COMMIT();
        for (int c = 0; c < NCHUNK; c++) {
            CP_WAIT(1);
            __syncthreads();
            if (c + 2 < NCHUNK) load_stage(c + 2);
            CP_COMMIT();
            const int4* At = reinterpret_cast<const int4*>(smem + (c % 3) * (STAGEB / 4));
            const int4* Bt = At + (A_BYTES / 16);
            #pragma unroll
            for (int u = 0; u < 8; u++) {               // 8 x 16B units = 32 ki
                int4 a4[8];
                #pragma unroll
                for (int i = 0; i < 8; i++) a4[i] = At[aIdx[i] + (u ^ aSw)];
                #pragma unroll
                for (int jh = 0; jh < 2; jh++) {        // b in two groups of 4 (reg pressure)
                    int4 b4[4];
                    #pragma unroll
                    for (int j = 0; j < 4; j++) b4[j] = Bt[bIdx[jh * 4 + j] + (u ^ bSw)];
                    #pragma unroll
                    for (int i = 0; i < 8; i++) {
                        #pragma unroll
                        for (int j = 0; j < 4; j++) {
                            int jj = jh * 4 + j;
                            acc[i][jj] = __dp4a(a4[i].x, b4[j].x, acc[i][jj]);
                            acc[i][jj] = __dp4a(a4[i].y, b4[j].y, acc[i][jj]);
                            acc[i][jj] = __dp4a(a4[i].z, b4[j].z, acc[i][jj]);
                            acc[i][jj] = __dp4a(a4[i].w, b4[j].w, acc[i][jj]);
                        }
                    }
                }
            }
        }

        // epilogue: m = m0+ty+16i, n = n0+tx+8j
        float fw[8], fb[8];
        #pragma unroll
        for (int j = 0; j < 8; j++) {
            int n = n0 + tx + 8 * j;
            fw[j] = g_sw[n];
            fb[j] = __ldg(&bias[n]) / __ldg(&scales[n]);
        }
        #pragma unroll
        for (int i = 0; i < 8; i++) {
            int m = m0 + ty + 16 * i;
            float fa = g_sa[m];
            float* orow = out + (size_t)m * N_ROWS + n0 + tx;
            #pragma unroll
            for (int j = 0; j < 8; j++)
                orow[8 * j] = acc[i][j] * fa * fw[j] + fb[j];
        }
    } else {
        // ================= IMMA half: n in [64,128) =================
        const int wi  = wid - 4;
        const int wm  = wi >> 1;        // m offset wm*64
        const int wn  = wi & 1;         // n offset 64 + wn*32
        const int g   = lane >> 2;
        const int tig = lane & 3;
        int acc[4][4][4];
        #pragma unroll
        for (int i = 0; i < 4; i++)
            #pragma unroll
            for (int j = 0; j < 4; j++)
                #pragma unroll
                for (int k = 0; k < 4; k++) acc[i][j][k] = 0;

        // ldmatrix lane bases (R5-proven): A r = wm*64+mt*16+(lane&7)+((lane>>3)&1)*8
        uint32_t baseA[4]; int rqA[4];
        const int chA = lane >> 4;
        #pragma unroll
        for (int mt = 0; mt < 4; mt++) {
            int r = wm * 64 + mt * 16 + (lane & 7) + ((lane >> 3) & 1) * 8;
            baseA[mt] = (uint32_t)(r * 128);
            rqA[mt]   = r & 7;
        }
        uint32_t baseB[2]; int rqB[2];
        const int chB = (lane >> 3) & 1;
        #pragma unroll
        for (int p = 0; p < 2; p++) {
            int r = 64 + wn * 32 + p * 16 + ((lane >> 4) & 1) * 8 + (lane & 7);
            baseB[p] = (uint32_t)(A_BYTES + r * 128);
            rqB[p]   = r & 7;
        }

        load_stage(0); CP_COMMIT();
        load_stage(1); CP_COMMIT();
        for (int c = 0; c < NCHUNK; c++) {
            CP_WAIT(1);
            __syncthreads();
            if (c + 2 < NCHUNK) load_stage(c + 2);
            CP_COMMIT();
            const uint32_t sB = sb + (uint32_t)(c % 3) * STAGEB;
            #pragma unroll
            for (int ks = 0; ks < 4; ks++) {            // 4 x k32 per 128B chunk
                uint32_t a[4][4], b[4][2];
                #pragma unroll
                for (int mt = 0; mt < 4; mt++)
                    ldsm4(a[mt][0], a[mt][1], a[mt][2], a[mt][3],
                          sB + baseA[mt] + (((2 * ks + chA) ^ rqA[mt]) << 4));
                #pragma unroll
                for (int p = 0; p < 2; p++)
                    ldsm4(b[2*p][0], b[2*p][1], b[2*p+1][0], b[2*p+1][1],
                          sB + baseB[p] + (((2 * ks + chB) ^ rqB[p]) << 4));
                #pragma unroll
                for (int mt = 0; mt < 4; mt++)
                    #pragma unroll
                    for (int nt = 0; nt < 4; nt++)
                        imma16832(acc[mt][nt], a[mt], b[nt]);
            }
        }

        float fw[4][2], fb[4][2];
        #pragma unroll
        for (int nt = 0; nt < 4; nt++) {
            int n = n0 + 64 + wn * 32 + nt * 8 + 2 * tig;
            fw[nt][0] = g_sw[n];
            fw[nt][1] = g_sw[n + 1];
            fb[nt][0] = __ldg(&bias[n])     / __ldg(&scales[n]);
            fb[nt][1] = __ldg(&bias[n + 1]) / __ldg(&scales[n + 1]);
        }
        #pragma unroll
        for (int mt = 0; mt < 4; mt++) {
            int mA = m0 + wm * 64 + mt * 16 + g;
            float saA = g_sa[mA];
            float saB = g_sa[mA + 8];
            #pragma unroll
            for (int nt = 0; nt < 4; nt++) {
                int n = n0 + 64 + wn * 32 + nt * 8 + 2 * tig;
                float2 o0, o1;
                o0.x = acc[mt][nt][0] * saA * fw[nt][0] + fb[nt][0];
                o0.y = acc[mt][nt][1] * saA * fw[nt][1] + fb[nt][1];
                o1.x = acc[mt][nt][2] * saB * fw[nt][0] + fb[nt][0];
                o1.y = acc[mt][nt][3] * saB * fw[nt][1] + fb[nt][1];
                *reinterpret_cast<float2*>(out + (size_t)mA       * N_ROWS + n) = o0;
                *reinterpret_cast<float2*>(out + (size_t)(mA + 8) * N_ROWS + n) = o1;
            }
        }
    }
}

// ---------------- launch ----------------
extern "C" void kernel_launch(void* const* d_in, const int* in_sizes, int n_in,
                              void* d_out, int out_size)
{
    const float* x      = (const float*)d_in[0];
    const float* weight = (const float*)d_in[1];
    const float* bias   = (const float*)d_in[2];
    const float* scales = (const float*)d_in[3];
    float* out = (float*)d_out;

    cudaFuncSetAttribute(gemm_hybrid_kernel,
                         cudaFuncAttributeMaxDynamicSharedMemorySize, SMEM_BYTES);

    quant_fused_kernel<<<M_ROWS + N_ROWS, 256>>>(x, weight, scales);

    dim3 grid(N_ROWS / 128, M_ROWS / 128);   // (32, 64)
    gemm_hybrid_kernel<<<grid, 256, SMEM_BYTES>>>(bias, scales, out);
}